// round 11
// baseline (speedup 1.0000x reference)
#include <cuda_runtime.h>
#include <cuda_bf16.h>
#include <math.h>

// Problem constants (fixed by the reference)
#define BB 4
#define TT 512
#define TP 1024
#define CC 32
#define KK 128
#define NW 16                 // 32-bit words per 512-event mask
#define GPROWS (TT + CC)      // 544 GP rows per batch
#define NTHREADS 512
#define TP_PER_BLOCK 16       // 1 tp per warp
#define EPSF 2.220446049250313e-16f

struct Smem {
    float    gp[GPROWS * CC];        // 68 KB: pa[e][c]*prefix-sum exp(pd*pt)
    float    pd[CC * CC];            // softplus(delta)[e][c]+EPS
    float    pa[CC * CC];            // softplus(alpha)[e][c]
    float    t[TT];                  // batch's sorted event times
    float    gtg[TT];                // times grouped by event type
    int      ev[TT];                 // event ids
    unsigned mask[(NW + 1) * CC];    // [w][e] bitmask (word 16 = 0 pad)
    int      wpref[(NW + 1) * CC];   // [w][e] count below word w (word 16 = n)
    int      obase[CC];              // group start in gtg
    int      gbase[CC];              // group start row in gp
    int      gn[CC];                 // group sizes
    float    ex[KK];                 // cf logits -> exp(cf - max)
    int      ftc_s[KK];
    float    part[4 * CC];           // den partials (quarters, fixed order)
    float    pf[KK];                 // fine probs
    float    spmu[CC];               // softplus(mu)
};

// fast softplus: abs err ~1e-6; amplified by pt<=25.6 in exponent -> <=2.5e-5 rel (ok vs 1e-3)
__device__ __forceinline__ float softplusf(float x) {
    return __logf(1.0f + __expf(x));
}

extern __shared__ char smem_raw[];

// One fused kernel: block = (tp-chunk, batch), 2 blocks co-resident per SM.
// Each block rebuilds its batch's setup in shared (redundant, parallel),
// then evaluates 16 tp's (1 per warp).
__global__ __launch_bounds__(NTHREADS, 2) void fused_kernel(
    const int*   __restrict__ past_event,   // [B,T]
    const float* __restrict__ past_time,    // [B,T]
    const float* __restrict__ time_tensor,  // [B,TP]
    const float* __restrict__ mu,           // [C]
    const float* __restrict__ alpha,        // [C,C]
    const float* __restrict__ delta,        // [C,C]
    const float* __restrict__ cf,           // [K]
    const int*   __restrict__ ftc,          // [K]
    float*       __restrict__ out)          // [B,TP,K]
{
    Smem* s = reinterpret_cast<Smem*>(smem_raw);
    const int b    = blockIdx.y;
    const int tid  = threadIdx.x;
    const int lane = tid & 31;
    const int wrp  = tid >> 5;               // 0..15

    // ---- phase 1: global loads + softplus tables ----
    if (tid < TT) {
        s->ev[tid] = past_event[b * TT + tid];
        s->t[tid]  = past_time [b * TT + tid];
    }
    for (int i = tid; i < CC * CC; i += NTHREADS) {
        s->pa[i] = softplusf(alpha[i]);
        s->pd[i] = softplusf(delta[i]) + EPSF;
    }
    if (tid < CC) s->spmu[tid] = softplusf(mu[tid]);
    if (tid < KK) { s->ex[tid] = cf[tid]; s->ftc_s[tid] = ftc[tid]; }
    __syncthreads();

    // ---- phase 2: event bitmasks via ballot (16 windows, 16 warps -> 1 round) ----
    {
        int evv = s->ev[wrp * 32 + lane];
        unsigned mym = 0u;
#pragma unroll
        for (int e = 0; e < CC; e++) {
            unsigned m = __ballot_sync(0xffffffffu, evv == e);
            if (lane == e) mym = m;
        }
        s->mask[wrp * CC + lane] = mym;
    }
    __syncthreads();

    // ---- phase 3a: warp0 = word-prefix + group-base scans; warp1 = cf max+exp ----
    if (wrp == 0) {
        int c = 0;
#pragma unroll
        for (int w = 0; w < NW; w++) {
            s->wpref[w * CC + lane] = c;
            c += __popc(s->mask[w * CC + lane]);
        }
        s->wpref[NW * CC + lane] = c;      // total n
        s->mask [NW * CC + lane] = 0u;     // pad word for J=512
        s->gn[lane] = c;
        int on = c, og = c + 1;            // inclusive scans
#pragma unroll
        for (int d = 1; d < 32; d <<= 1) {
            int v1 = __shfl_up_sync(0xffffffffu, on, d);
            int v2 = __shfl_up_sync(0xffffffffu, og, d);
            if (lane >= d) { on += v1; og += v2; }
        }
        s->obase[lane] = on - c;           // exclusive
        s->gbase[lane] = og - (c + 1);
    } else if (wrp == 1) {
        float a0 = s->ex[lane],      a1 = s->ex[lane + 32];
        float a2 = s->ex[lane + 64], a3 = s->ex[lane + 96];
        float m = fmaxf(fmaxf(a0, a1), fmaxf(a2, a3));
#pragma unroll
        for (int d = 16; d >= 1; d >>= 1)
            m = fmaxf(m, __shfl_xor_sync(0xffffffffu, m, d));
        float v0 = __expf(a0 - m), v1 = __expf(a1 - m);
        float v2 = __expf(a2 - m), v3 = __expf(a3 - m);
        __syncwarp();
        s->ex[lane] = v0; s->ex[lane + 32] = v1;
        s->ex[lane + 64] = v2; s->ex[lane + 96] = v3;
    }
    __syncthreads();

    // ---- phase 3b: scatter times into grouped order; den partials (fixed order) ----
    if (tid < TT) {
        int t = tid;
        int e = s->ev[t];
        int w = t >> 5, rb = t & 31;
        int j = s->wpref[w * CC + e]
              + __popc(s->mask[w * CC + e] & ((1u << rb) - 1u));
        s->gtg[s->obase[e] + j] = s->t[t];
    }
    if (wrp < 4) {   // warp q sums quarter q of k-space per c-lane, ascending k
        float d = 0.f;
#pragma unroll
        for (int kk = 0; kk < 32; kk++) {
            int k = wrp * 32 + kk;
            if (s->ftc_s[k] == lane) d += s->ex[k];
        }
        s->part[wrp * CC + lane] = d;
    }
    __syncthreads();

    // ---- phase 4: fine probs; GP prefix build (warp wrp -> groups wrp, wrp+16) ----
    if (tid < KK) {
        int c = s->ftc_s[tid];
        float den = ((s->part[c] + s->part[CC + c]) + s->part[2 * CC + c])
                  + s->part[3 * CC + c];
        s->pf[tid] = s->ex[tid] / den;
    }
#pragma unroll
    for (int q = 0; q < 2; q++) {
        const int e  = wrp + 16 * q;
        const float pdv = s->pd[e * CC + lane];
        const float pav = s->pa[e * CC + lane];
        const int n  = s->gn[e];
        const int ob = s->obase[e];
        float* g = &s->gp[s->gbase[e] * CC];
        g[lane] = 0.f;                       // j = 0 row
        float acc = 0.f;
        int j = 0;
        for (; j + 4 <= n; j += 4) {         // pipeline 4 exps ahead of FADD chain
            float x0 = __expf(pdv * s->gtg[ob + j]);
            float x1 = __expf(pdv * s->gtg[ob + j + 1]);
            float x2 = __expf(pdv * s->gtg[ob + j + 2]);
            float x3 = __expf(pdv * s->gtg[ob + j + 3]);
            acc += x0; g[(j + 1) * CC + lane] = acc * pav;
            acc += x1; g[(j + 2) * CC + lane] = acc * pav;
            acc += x2; g[(j + 3) * CC + lane] = acc * pav;
            acc += x3; g[(j + 4) * CC + lane] = acc * pav;
        }
        for (; j < n; j++) {
            acc += __expf(pdv * s->gtg[ob + j]);
            g[(j + 1) * CC + lane] = acc * pav;
        }
    }
    __syncthreads();

    // ---- phase 5: main evaluation. warp handles 1 tp; lane = c ----
    const int tp = blockIdx.x * TP_PER_BLOCK + wrp;
    const float tt  = time_tensor[b * TP + tp];
    const float ntt = -tt;

    // branchless binary count: J = #events with (tt - pt) > EPS (warp-uniform)
    int pos = 0;
#pragma unroll
    for (int st = 512; st >= 1; st >>= 1) {
        int cand = pos + st;
        if (cand <= TT && (tt - s->t[cand - 1] > EPSF)) pos = cand;
    }

    // lane l resolves GP row for event-type e = l via bitmask popcount
    int rowl;
    {
        int J = pos, wd = J >> 5, rb = J & 31;
        int jl = s->wpref[wd * CC + lane]
               + __popc(s->mask[wd * CC + lane] & ((1u << rb) - 1u));
        rowl = s->gbase[lane] + jl;
    }

    float acc = 0.f;
#pragma unroll
    for (int e = 0; e < CC; e++) {
        float pdv = s->pd[e * CC + lane];
        int r = __shfl_sync(0xffffffffu, rowl, e);
        float gpv = s->gp[r * CC + lane];               // conflict-free LDS
        acc = fmaf(__expf(pdv * ntt), gpv, acc);
    }

    // epilogue tables + scatter: out[k] = (acc[ftc[k]] + spmu[c]) * pfine[k]
    float* o = out + (b * TP + tp) * KK;
#pragma unroll
    for (int j = 0; j < 4; j++) {
        int k = lane + 32 * j;
        int c = s->ftc_s[k];
        float v = __shfl_sync(0xffffffffu, acc, c);
        o[k] = (v + s->spmu[c]) * s->pf[k];
    }
}

// ---------------- launch ----------------
extern "C" void kernel_launch(void* const* d_in, const int* in_sizes, int n_in,
                              void* d_out, int out_size)
{
    const int*   past_event  = (const int*)  d_in[0];
    const float* past_time   = (const float*)d_in[1];
    const float* time_tensor = (const float*)d_in[2];
    const float* mu          = (const float*)d_in[3];
    const float* alpha       = (const float*)d_in[4];
    const float* delta       = (const float*)d_in[5];
    const float* cf_logits   = (const float*)d_in[6];
    const int*   ftc         = (const int*)  d_in[7];
    float* out = (float*)d_out;

    static_assert(sizeof(Smem) < 112 * 1024, "smem too large for 2 blocks/SM");
    cudaFuncSetAttribute(fused_kernel,
                         cudaFuncAttributeMaxDynamicSharedMemorySize,
                         (int)sizeof(Smem));
    fused_kernel<<<dim3(TP / TP_PER_BLOCK, BB), NTHREADS, sizeof(Smem)>>>(
        past_event, past_time, time_tensor, mu, alpha, delta, cf_logits, ftc, out);
}

// round 12
// speedup vs baseline: 1.2113x; 1.2113x over previous
#include <cuda_runtime.h>
#include <cuda_bf16.h>
#include <math.h>

// Problem constants (fixed by the reference)
#define BB 4
#define TT 512
#define TP 1024
#define CC 32
#define KK 128
#define NW 16                 // 32-bit words per 512-event mask
#define GPROWS (TT + CC)      // 544 GP rows per batch
#define NTHREADS 512
#define TP_PER_BLOCK 32       // 2 tp per warp
#define LOG2E 1.4426950408889634f
#define EPSF 2.220446049250313e-16f

struct Smem {
    float    gp[GPROWS * CC];        // 68 KB: pa[e][c]*prefix-sum exp(pd*pt)
    float    pd2[CC * CC];           // (softplus(delta)[e][c]+EPS) * log2(e)
    float    pa[CC * CC];            // softplus(alpha)[e][c]
    float    t[TT];                  // batch's sorted event times
    float    gtg[TT];                // times grouped by event type
    int      ev[TT];                 // event ids
    unsigned mask[(NW + 1) * CC];    // [w][e] bitmask (word 16 = 0 pad)
    int      wpref[(NW + 1) * CC];   // [w][e] count below word w (word 16 = n)
    int      obase[CC];              // group start in gtg
    int      gbase[CC];              // group start row in gp
    int      gn[CC];                 // group sizes
    float    ex[KK];                 // cf logits -> exp(cf - max)
    int      ftc_s[KK];
    float    part[4 * CC];           // den partials (quarters, fixed order)
    float    pf[KK];                 // fine probs
    float    spmu[CC];               // softplus(mu)
};

// fast softplus: abs err ~1e-6; amplified by pt<=25.6 in exponent -> <=2.5e-5 rel (ok vs 1e-3)
__device__ __forceinline__ float softplusf(float x) {
    return __logf(1.0f + __expf(x));
}

extern __shared__ char smem_raw[];

// One fused kernel: block = (tp-chunk, batch), 1 block/SM (128 blocks).
// Each block rebuilds its batch's setup in shared, then evaluates 32 tp's (2/warp).
__global__ __launch_bounds__(NTHREADS) void fused_kernel(
    const int*   __restrict__ past_event,   // [B,T]
    const float* __restrict__ past_time,    // [B,T]
    const float* __restrict__ time_tensor,  // [B,TP]
    const float* __restrict__ mu,           // [C]
    const float* __restrict__ alpha,        // [C,C]
    const float* __restrict__ delta,        // [C,C]
    const float* __restrict__ cf,           // [K]
    const int*   __restrict__ ftc,          // [K]
    float*       __restrict__ out)          // [B,TP,K]
{
    Smem* s = reinterpret_cast<Smem*>(smem_raw);
    const int b    = blockIdx.y;
    const int tid  = threadIdx.x;
    const int lane = tid & 31;
    const int wrp  = tid >> 5;               // 0..15

    // ---- phase 1: global loads + softplus tables ----
    if (tid < TT) {
        s->ev[tid] = past_event[b * TT + tid];
        s->t[tid]  = past_time [b * TT + tid];
    }
    for (int i = tid; i < CC * CC; i += NTHREADS) {
        s->pa[i]  = softplusf(alpha[i]);
        s->pd2[i] = (softplusf(delta[i]) + EPSF) * LOG2E;
    }
    if (tid < CC) s->spmu[tid] = softplusf(mu[tid]);
    if (tid < KK) { s->ex[tid] = cf[tid]; s->ftc_s[tid] = ftc[tid]; }
    __syncthreads();

    // ---- phase 2: event bitmasks via ballot (16 windows, 16 warps -> 1 round) ----
    {
        int evv = s->ev[wrp * 32 + lane];
        unsigned mym = 0u;
#pragma unroll
        for (int e = 0; e < CC; e++) {
            unsigned m = __ballot_sync(0xffffffffu, evv == e);
            if (lane == e) mym = m;
        }
        s->mask[wrp * CC + lane] = mym;
    }
    __syncthreads();

    // ---- phase 3a: warp0 = word-prefix + group-base scans; warp1 = cf max+exp ----
    if (wrp == 0) {
        int c = 0;
#pragma unroll
        for (int w = 0; w < NW; w++) {
            s->wpref[w * CC + lane] = c;
            c += __popc(s->mask[w * CC + lane]);
        }
        s->wpref[NW * CC + lane] = c;      // total n
        s->mask [NW * CC + lane] = 0u;     // pad word for J=512
        s->gn[lane] = c;
        int on = c, og = c + 1;            // inclusive scans
#pragma unroll
        for (int d = 1; d < 32; d <<= 1) {
            int v1 = __shfl_up_sync(0xffffffffu, on, d);
            int v2 = __shfl_up_sync(0xffffffffu, og, d);
            if (lane >= d) { on += v1; og += v2; }
        }
        s->obase[lane] = on - c;           // exclusive
        s->gbase[lane] = og - (c + 1);
    } else if (wrp == 1) {
        float a0 = s->ex[lane],      a1 = s->ex[lane + 32];
        float a2 = s->ex[lane + 64], a3 = s->ex[lane + 96];
        float m = fmaxf(fmaxf(a0, a1), fmaxf(a2, a3));
#pragma unroll
        for (int d = 16; d >= 1; d >>= 1)
            m = fmaxf(m, __shfl_xor_sync(0xffffffffu, m, d));
        float v0 = __expf(a0 - m), v1 = __expf(a1 - m);
        float v2 = __expf(a2 - m), v3 = __expf(a3 - m);
        __syncwarp();
        s->ex[lane] = v0; s->ex[lane + 32] = v1;
        s->ex[lane + 64] = v2; s->ex[lane + 96] = v3;
    }
    __syncthreads();

    // ---- phase 3b: scatter times into grouped order; den partials (fixed order) ----
    if (tid < TT) {
        int t = tid;
        int e = s->ev[t];
        int w = t >> 5, rb = t & 31;
        int j = s->wpref[w * CC + e]
              + __popc(s->mask[w * CC + e] & ((1u << rb) - 1u));
        s->gtg[s->obase[e] + j] = s->t[t];
    }
    if (wrp < 4) {   // warp q sums quarter q of k-space per c-lane, ascending k
        float d = 0.f;
#pragma unroll
        for (int kk = 0; kk < 32; kk++) {
            int k = wrp * 32 + kk;
            if (s->ftc_s[k] == lane) d += s->ex[k];
        }
        s->part[wrp * CC + lane] = d;
    }
    __syncthreads();

    // ---- phase 4: fine probs; GP prefix build (warp wrp -> groups wrp, wrp+16) ----
    if (tid < KK) {
        int c = s->ftc_s[tid];
        float den = ((s->part[c] + s->part[CC + c]) + s->part[2 * CC + c])
                  + s->part[3 * CC + c];
        s->pf[tid] = s->ex[tid] / den;
    }
#pragma unroll
    for (int q = 0; q < 2; q++) {
        const int e  = wrp + 16 * q;
        const float pdv = s->pd2[e * CC + lane];   // includes log2e
        const float pav = s->pa[e * CC + lane];
        const int n  = s->gn[e];
        const int ob = s->obase[e];
        float* g = &s->gp[s->gbase[e] * CC];
        g[lane] = 0.f;                       // j = 0 row
        float acc = 0.f;
        int j = 0;
        for (; j + 4 <= n; j += 4) {         // pipeline 4 exps ahead of FADD chain
            float x0 = exp2f(pdv * s->gtg[ob + j]);
            float x1 = exp2f(pdv * s->gtg[ob + j + 1]);
            float x2 = exp2f(pdv * s->gtg[ob + j + 2]);
            float x3 = exp2f(pdv * s->gtg[ob + j + 3]);
            acc += x0; g[(j + 1) * CC + lane] = acc * pav;
            acc += x1; g[(j + 2) * CC + lane] = acc * pav;
            acc += x2; g[(j + 3) * CC + lane] = acc * pav;
            acc += x3; g[(j + 4) * CC + lane] = acc * pav;
        }
        for (; j < n; j++) {
            acc += exp2f(pdv * s->gtg[ob + j]);
            g[(j + 1) * CC + lane] = acc * pav;
        }
    }
    __syncthreads();

    // ---- phase 5: main evaluation. warp handles 2 tp's; lane = c ----
    const int tp0 = (blockIdx.x * 16 + wrp) * 2;
    float tt[2], ntt[2];
#pragma unroll
    for (int i = 0; i < 2; i++) {
        tt[i]  = time_tensor[b * TP + tp0 + i];
        ntt[i] = -tt[i];
    }

    // branchless binary count: J = #events with (tt - pt) > EPS (warp-uniform)
    int pos[2] = {0, 0};
#pragma unroll
    for (int st = 512; st >= 1; st >>= 1) {
#pragma unroll
        for (int i = 0; i < 2; i++) {
            int cand = pos[i] + st;
            if (cand <= TT && (tt[i] - s->t[cand - 1] > EPSF)) pos[i] = cand;
        }
    }

    // lane l resolves GP row for event-type e = l via bitmask popcount
    int rowl[2];
#pragma unroll
    for (int i = 0; i < 2; i++) {
        int J = pos[i], wd = J >> 5, rb = J & 31;
        int jl = s->wpref[wd * CC + lane]
               + __popc(s->mask[wd * CC + lane] & ((1u << rb) - 1u));
        rowl[i] = s->gbase[lane] + jl;
    }

    // batch-8 software-pipelined e-loop: shfl rows, batch LDS, then MUFU+FFMA
    float acc[2] = {0.f, 0.f};
#pragma unroll
    for (int eb = 0; eb < CC; eb += 8) {
        int   r0[8], r1[8];
        float g0[8], g1[8], pdv[8];
#pragma unroll
        for (int u = 0; u < 8; u++) {
            r0[u] = __shfl_sync(0xffffffffu, rowl[0], eb + u);
            r1[u] = __shfl_sync(0xffffffffu, rowl[1], eb + u);
        }
#pragma unroll
        for (int u = 0; u < 8; u++) {
            pdv[u] = s->pd2[(eb + u) * CC + lane];
            g0[u]  = s->gp[r0[u] * CC + lane];   // conflict-free LDS
            g1[u]  = s->gp[r1[u] * CC + lane];
        }
#pragma unroll
        for (int u = 0; u < 8; u++) {
            acc[0] = fmaf(exp2f(pdv[u] * ntt[0]), g0[u], acc[0]);
            acc[1] = fmaf(exp2f(pdv[u] * ntt[1]), g1[u], acc[1]);
        }
    }

    // epilogue: out[k] = (acc[ftc[k]] + spmu[c]) * pfine[k]
#pragma unroll
    for (int i = 0; i < 2; i++) {
        float* o = out + (b * TP + tp0 + i) * KK;
#pragma unroll
        for (int j = 0; j < 4; j++) {
            int k = lane + 32 * j;
            int c = s->ftc_s[k];
            float v = __shfl_sync(0xffffffffu, acc[i], c);
            o[k] = (v + s->spmu[c]) * s->pf[k];
        }
    }
}

// ---------------- launch ----------------
extern "C" void kernel_launch(void* const* d_in, const int* in_sizes, int n_in,
                              void* d_out, int out_size)
{
    const int*   past_event  = (const int*)  d_in[0];
    const float* past_time   = (const float*)d_in[1];
    const float* time_tensor = (const float*)d_in[2];
    const float* mu          = (const float*)d_in[3];
    const float* alpha       = (const float*)d_in[4];
    const float* delta       = (const float*)d_in[5];
    const float* cf_logits   = (const float*)d_in[6];
    const int*   ftc         = (const int*)  d_in[7];
    float* out = (float*)d_out;

    static_assert(sizeof(Smem) < 200 * 1024, "smem too large");
    cudaFuncSetAttribute(fused_kernel,
                         cudaFuncAttributeMaxDynamicSharedMemorySize,
                         (int)sizeof(Smem));
    fused_kernel<<<dim3(TP / TP_PER_BLOCK, BB), NTHREADS, sizeof(Smem)>>>(
        past_event, past_time, time_tensor, mu, alpha, delta, cf_logits, ftc, out);
}